// round 2
// baseline (speedup 1.0000x reference)
#include <cuda_runtime.h>
#include <cuda_bf16.h>
#include <math.h>

#define NNODES 20000
#define NGROUP 400
#define MAXG   512
#define D_IN   128
#define H1     256
#define H2     256
#define D_OUT  128

// ---------------- scratch (static device allocations; no cudaMalloc) ----------
__device__ float g_bufA[NNODES * 256];
__device__ float g_bufB[NNODES * 256];
__device__ int   g_members[NGROUP * MAXG];
__device__ int   g_cnt[NGROUP];
__device__ float g_dis[NNODES];
__device__ int   g_is64;   // 1 if idx buffer is int64, 0 if int32

// ---------------- 0) dtype detection for idx ---------------------------------
// The reference declares int64 but JAX (x64 disabled) silently yields int32.
// Sample 256 elements interpreted as int64: any value outside [0,NGROUP) or
// nonzero high word ==> the buffer is int32.
__global__ void detect_dtype(const int* __restrict__ idx32, int n) {
    int i = threadIdx.x;            // 256 threads, 1 block
    // as int64: element i occupies words (2i, 2i+1); both reads are within
    // the first n int32 words for i < 128, and within 2n words always if the
    // buffer really is int64. Restrict to i < n/2 so it's safe either way.
    bool bad = false;
    if (i < n / 2) {
        int lo = idx32[2 * i];
        int hi = idx32[2 * i + 1];
        bad = (hi != 0) || (lo < 0) || (lo >= NGROUP);
    }
    unsigned m = __ballot_sync(0xffffffffu, bad);
    __shared__ unsigned s_any[8];
    if ((threadIdx.x & 31) == 0) s_any[threadIdx.x >> 5] = m;
    __syncthreads();
    if (threadIdx.x == 0) {
        unsigned any = 0;
#pragma unroll
        for (int w = 0; w < 8; w++) any |= s_any[w];
        g_is64 = (any == 0) ? 1 : 0;
    }
}

// ---------------- 1) group build: ordered compaction per group ----------------
// Block g scans idx[0..n) and writes the member list in node-index order.
// dis[i] = rsqrt(rank+1)   (rank+1 == in-degree incl. self loop).
__global__ __launch_bounds__(256) void build_groups(const void* __restrict__ idx_raw, int n) {
    const int g    = blockIdx.x;
    const int tid  = threadIdx.x;
    const int lane = tid & 31;
    const int warp = tid >> 5;
    const int is64 = g_is64;
    const int*       idx32 = (const int*)idx_raw;
    const long long* idx64 = (const long long*)idx_raw;

    __shared__ int warp_sums[8];
    __shared__ int s_base;
    if (tid == 0) s_base = 0;
    __syncthreads();

    for (int t0 = 0; t0 < n; t0 += 256) {
        int i = t0 + tid;
        int v = -1;
        if (i < n) v = is64 ? (int)idx64[i] : idx32[i];
        bool flag = (v == g);
        unsigned mask = __ballot_sync(0xffffffffu, flag);
        int wprefix = __popc(mask & ((1u << lane) - 1u));
        if (lane == 0) warp_sums[warp] = __popc(mask);
        __syncthreads();
        int woff = 0;
#pragma unroll
        for (int w = 0; w < 8; w++) if (w < warp) woff += warp_sums[w];
        int tile_total = 0;
#pragma unroll
        for (int w = 0; w < 8; w++) tile_total += warp_sums[w];
        if (flag) {
            int pos = s_base + woff + wprefix;
            g_members[g * MAXG + pos] = i;
            g_dis[i] = rsqrtf((float)(pos + 1));
        }
        __syncthreads();
        if (tid == 0) s_base += tile_total;
        __syncthreads();
    }
    if (tid == 0) g_cnt[g] = s_base;
}

// ---------------- 2) fp32 SGEMM: C[M,Nc] = A[M,K] @ B[K,Nc] -------------------
// BM=BN=64, BK=16, 256 threads, 4x4 register micro-tile.
__global__ __launch_bounds__(256) void sgemm(const float* __restrict__ A,
                                             const float* __restrict__ B,
                                             float* __restrict__ C,
                                             int M, int K, int Nc) {
    __shared__ float As[16][68];  // [k][m]
    __shared__ float Bs[16][68];  // [k][n]
    const int bm = blockIdx.x * 64;
    const int bn = blockIdx.y * 64;
    const int tid = threadIdx.x;
    const int tm = (tid >> 4) * 4;   // 0..60
    const int tn = (tid & 15) * 4;   // 0..60

    float acc[4][4] = {};

    for (int k0 = 0; k0 < K; k0 += 16) {
        // load A tile (64 x 16)
#pragma unroll
        for (int r = 0; r < 4; r++) {
            int i  = tid + r * 256;
            int m  = i >> 4;
            int kk = i & 15;
            int gr = bm + m;
            As[kk][m] = (gr < M) ? A[(size_t)gr * K + k0 + kk] : 0.0f;
        }
        // load B tile (16 x 64)
#pragma unroll
        for (int r = 0; r < 4; r++) {
            int i  = tid + r * 256;
            int kk = i >> 6;
            int n  = i & 63;
            Bs[kk][n] = B[(size_t)(k0 + kk) * Nc + bn + n];
        }
        __syncthreads();
#pragma unroll
        for (int kk = 0; kk < 16; kk++) {
            float4 a4 = *reinterpret_cast<const float4*>(&As[kk][tm]);
            float4 b4 = *reinterpret_cast<const float4*>(&Bs[kk][tn]);
            float a[4] = {a4.x, a4.y, a4.z, a4.w};
            float b[4] = {b4.x, b4.y, b4.z, b4.w};
#pragma unroll
            for (int i = 0; i < 4; i++)
#pragma unroll
                for (int j = 0; j < 4; j++)
                    acc[i][j] = fmaf(a[i], b[j], acc[i][j]);
        }
        __syncthreads();
    }
#pragma unroll
    for (int i = 0; i < 4; i++) {
        int gr = bm + tm + i;
        if (gr < M) {
            float4 o;
            o.x = acc[i][0]; o.y = acc[i][1]; o.z = acc[i][2]; o.w = acc[i][3];
            *reinterpret_cast<float4*>(&C[(size_t)gr * Nc + bn + tn]) = o;
        }
    }
}

// ---------------- 3) per-group prefix scan + bias + relu ----------------------
// out[j] = relu( dis_j * sum_{i<=j in group} dis_i * H[i]  + b )
// One block per group; one thread per feature column (blockDim == D).
__global__ void scan_relu(const float* __restrict__ H, const float* __restrict__ bias,
                          float* __restrict__ out, int D) {
    __shared__ int   s_mem[MAXG];
    __shared__ float s_dis[MAXG];
    const int g = blockIdx.x;
    const int c = g_cnt[g];
    for (int m = threadIdx.x; m < c; m += blockDim.x) {
        int i = g_members[g * MAXG + m];
        s_mem[m] = i;
        s_dis[m] = g_dis[i];
    }
    __syncthreads();
    const int f = threadIdx.x;
    float acc = 0.0f;
    const float bf = bias[f];
    for (int m = 0; m < c; m++) {
        int   i = s_mem[m];
        float d = s_dis[m];
        acc = fmaf(d, H[(size_t)i * D + f], acc);
        out[(size_t)i * D + f] = fmaxf(fmaf(d, acc, bf), 0.0f);
    }
}

// ---------------- 4) LayerNorm over last dim (128) ----------------------------
__global__ __launch_bounds__(256) void layernorm128(const float* __restrict__ h,
                                                    const float* __restrict__ gamma,
                                                    const float* __restrict__ beta,
                                                    float* __restrict__ out, int n) {
    int row = blockIdx.x * (blockDim.x >> 5) + (threadIdx.x >> 5);
    if (row >= n) return;
    int lane = threadIdx.x & 31;
    float4 v = reinterpret_cast<const float4*>(h + (size_t)row * 128)[lane];
    float s = v.x + v.y + v.z + v.w;
#pragma unroll
    for (int o = 16; o; o >>= 1) s += __shfl_xor_sync(0xffffffffu, s, o);
    float mu = s * (1.0f / 128.0f);
    float dx = v.x - mu, dy = v.y - mu, dz = v.z - mu, dw = v.w - mu;
    float q = dx * dx + dy * dy + dz * dz + dw * dw;
#pragma unroll
    for (int o = 16; o; o >>= 1) q += __shfl_xor_sync(0xffffffffu, q, o);
    float inv = rsqrtf(q * (1.0f / 128.0f) + 1e-5f);
    float4 ga = reinterpret_cast<const float4*>(gamma)[lane];
    float4 be = reinterpret_cast<const float4*>(beta)[lane];
    float4 o4;
    o4.x = fmaf(dx * inv, ga.x, be.x);
    o4.y = fmaf(dy * inv, ga.y, be.y);
    o4.z = fmaf(dz * inv, ga.z, be.z);
    o4.w = fmaf(dw * inv, ga.w, be.w);
    reinterpret_cast<float4*>(out + (size_t)row * 128)[lane] = o4;
}

// ---------------- launch ------------------------------------------------------
extern "C" void kernel_launch(void* const* d_in, const int* in_sizes, int n_in,
                              void* d_out, int out_size) {
    const float* x     = (const float*)d_in[0];
    const void*  idx   = d_in[1];
    const float* W1    = (const float*)d_in[2];
    const float* b1    = (const float*)d_in[3];
    const float* W2    = (const float*)d_in[4];
    const float* b2    = (const float*)d_in[5];
    const float* W3    = (const float*)d_in[6];
    const float* b3    = (const float*)d_in[7];
    const float* gamma = (const float*)d_in[8];
    const float* beta  = (const float*)d_in[9];
    float* out = (float*)d_out;

    float* bufA = nullptr;
    float* bufB = nullptr;
    cudaGetSymbolAddress((void**)&bufA, g_bufA);
    cudaGetSymbolAddress((void**)&bufB, g_bufB);

    const int n = NNODES;
    const int mblk = (n + 63) / 64;  // 313

    detect_dtype<<<1, 256>>>((const int*)idx, n);
    build_groups<<<NGROUP, 256>>>(idx, n);

    // layer 1: x[20000,128] @ W1[128,256]
    sgemm<<<dim3(mblk, H1 / 64), 256>>>(x, W1, bufA, n, D_IN, H1);
    scan_relu<<<NGROUP, H1>>>(bufA, b1, bufB, H1);

    // layer 2: [20000,256] @ W2[256,256]
    sgemm<<<dim3(mblk, H2 / 64), 256>>>(bufB, W2, bufA, n, H1, H2);
    scan_relu<<<NGROUP, H2>>>(bufA, b2, bufB, H2);

    // layer 3: [20000,256] @ W3[256,128]
    sgemm<<<dim3(mblk, D_OUT / 64), 256>>>(bufB, W3, bufA, n, H2, D_OUT);
    scan_relu<<<NGROUP, D_OUT>>>(bufA, b3, bufB, D_OUT);

    // layernorm -> out
    layernorm128<<<(n + 7) / 8, 256>>>(bufB, gamma, beta, out, n);
}

// round 4
// speedup vs baseline: 1.5998x; 1.5998x over previous
#include <cuda_runtime.h>
#include <cuda_bf16.h>
#include <math.h>
#include <stdint.h>

#define NNODES 20000
#define NGROUP 400
#define MAXG   512

// ---------------- scratch (static device allocations; no cudaMalloc) ----------
__device__ float g_bufA[NNODES * 256];
__device__ float g_bufB[NNODES * 256];
__device__ int   g_members[NGROUP * MAXG];
__device__ int   g_cnt[NGROUP];
__device__ float g_dis[NNODES];
__device__ int   g_is64;   // 1 if idx buffer is int64, 0 if int32

// bf16 hi/lo transposed weights: [N][K] row-major
__device__ __nv_bfloat16 g_w1h[256 * 128], g_w1l[256 * 128];
__device__ __nv_bfloat16 g_w2h[256 * 256], g_w2l[256 * 256];
__device__ __nv_bfloat16 g_w3h[128 * 256], g_w3l[128 * 256];

__device__ __forceinline__ uint32_t pack_bf16x2(float a, float b) {
    __nv_bfloat162 t = __floats2bfloat162_rn(a, b);
    return *reinterpret_cast<uint32_t*>(&t);
}

// ---------------- 0) dtype detection for idx ---------------------------------
__global__ void detect_dtype(const int* __restrict__ idx32, int n) {
    int i = threadIdx.x;
    bool bad = false;
    if (i < n / 2) {
        int lo = idx32[2 * i];
        int hi = idx32[2 * i + 1];
        bad = (hi != 0) || (lo < 0) || (lo >= NGROUP);
    }
    unsigned m = __ballot_sync(0xffffffffu, bad);
    __shared__ unsigned s_any[8];
    if ((threadIdx.x & 31) == 0) s_any[threadIdx.x >> 5] = m;
    __syncthreads();
    if (threadIdx.x == 0) {
        unsigned any = 0;
#pragma unroll
        for (int w = 0; w < 8; w++) any |= s_any[w];
        g_is64 = (any == 0) ? 1 : 0;
    }
}

// ---------------- 1) group build (4 elems/thread/tile) ------------------------
__global__ __launch_bounds__(256) void build_groups(const void* __restrict__ idx_raw, int n) {
    const int g    = blockIdx.x;
    const int tid  = threadIdx.x;
    const int lane = tid & 31;
    const int warp = tid >> 5;
    const int is64 = g_is64;
    const int*       idx32 = (const int*)idx_raw;
    const long long* idx64 = (const long long*)idx_raw;

    __shared__ int warp_sums[8];
    __shared__ int s_base;
    if (tid == 0) s_base = 0;
    __syncthreads();

    for (int t0 = 0; t0 < n; t0 += 1024) {
        int i0 = t0 + tid * 4;
        int v[4];
        if (!is64 && i0 + 3 < n) {
            int4 q = *reinterpret_cast<const int4*>(&idx32[i0]);
            v[0] = q.x; v[1] = q.y; v[2] = q.z; v[3] = q.w;
        } else {
#pragma unroll
            for (int j = 0; j < 4; j++) {
                int i = i0 + j;
                v[j] = (i < n) ? (is64 ? (int)idx64[i] : idx32[i]) : -1;
            }
        }
        unsigned m[4];
#pragma unroll
        for (int j = 0; j < 4; j++) m[j] = __ballot_sync(0xffffffffu, v[j] == g);
        unsigned lt = (1u << lane) - 1u;
        int lanebase = 0, wtotal = 0;
#pragma unroll
        for (int j = 0; j < 4; j++) { lanebase += __popc(m[j] & lt); wtotal += __popc(m[j]); }
        if (lane == 0) warp_sums[warp] = wtotal;
        __syncthreads();
        int woff = 0, tile_total = 0;
#pragma unroll
        for (int w = 0; w < 8; w++) {
            if (w < warp) woff += warp_sums[w];
            tile_total += warp_sums[w];
        }
        int mycnt = 0;
#pragma unroll
        for (int j = 0; j < 4; j++) {
            if (v[j] == g) {
                int pos = s_base + woff + lanebase + mycnt;
                g_members[g * MAXG + pos] = i0 + j;
                g_dis[i0 + j] = rsqrtf((float)(pos + 1));
                mycnt++;
            }
        }
        __syncthreads();
        if (tid == 0) s_base += tile_total;
        __syncthreads();
    }
    if (tid == 0) g_cnt[g] = s_base;
}

// ---------------- 2) weight prep: transpose + bf16 hi/lo split ----------------
__global__ void prep_w(const float* __restrict__ W, __nv_bfloat16* __restrict__ oh,
                       __nv_bfloat16* __restrict__ ol, int K, int N) {
    int e = blockIdx.x * 256 + threadIdx.x;
    if (e >= K * N) return;
    int n = e / K, k = e - n * K;
    float v = W[(size_t)k * N + n];
    __nv_bfloat16 h = __float2bfloat16(v);
    oh[e] = h;
    ol[e] = __float2bfloat16(v - __bfloat162float(h));
}

// ---------------- 3) HMMA GEMM: C[M,N] = A[M,K] @ W^T, W = [N][K] bf16 hi/lo --
// mma.sync m16n8k16 bf16, fp32 accum, 3-split for fp32-grade precision.
// BM=128, BN=128, BK=32, 256 threads: warp grid 2(M)x4(N), warp tile 64x32.
#define LDMX4(r0, r1, r2, r3, addr) \
    asm volatile("ldmatrix.sync.aligned.m8n8.x4.shared.b16 {%0,%1,%2,%3}, [%4];" \
                 : "=r"(r0), "=r"(r1), "=r"(r2), "=r"(r3) : "r"(addr))
#define MMA16816(c, a, b) \
    asm volatile("mma.sync.aligned.m16n8k16.row.col.f32.bf16.bf16.f32 " \
                 "{%0,%1,%2,%3}, {%4,%5,%6,%7}, {%8,%9}, {%0,%1,%2,%3};" \
                 : "+f"((c)[0]), "+f"((c)[1]), "+f"((c)[2]), "+f"((c)[3]) \
                 : "r"((a)[0]), "r"((a)[1]), "r"((a)[2]), "r"((a)[3]), \
                   "r"((b)[0]), "r"((b)[1]))

__global__ __launch_bounds__(256) void gemm_mma(const float* __restrict__ A,
                                                const __nv_bfloat16* __restrict__ Wh,
                                                const __nv_bfloat16* __restrict__ Wl,
                                                float* __restrict__ C,
                                                int M, int K, int N) {
    __shared__ __nv_bfloat16 sAh[128][40];
    __shared__ __nv_bfloat16 sAl[128][40];
    __shared__ __nv_bfloat16 sBh[128][40];
    __shared__ __nv_bfloat16 sBl[128][40];

    const int tid  = threadIdx.x;
    const int wid  = tid >> 5;
    const int lane = tid & 31;
    const int bm   = blockIdx.x * 128;
    const int bn   = blockIdx.y * 128;
    const int wm   = (wid & 1) * 64;       // warp M offset in tile
    const int wn   = (wid >> 1) * 32;      // warp N offset in tile

    const __nv_bfloat16* WhB = Wh + (size_t)bn * K;
    const __nv_bfloat16* WlB = Wl + (size_t)bn * K;

    float acc[4][4][4];
#pragma unroll
    for (int i = 0; i < 4; i++)
#pragma unroll
        for (int j = 0; j < 4; j++)
#pragma unroll
            for (int q = 0; q < 4; q++) acc[i][j][q] = 0.0f;

    const int lrow = lane & 15;
    const int lcol = (lane >> 4) << 3;

    for (int kc = 0; kc < K; kc += 32) {
        __syncthreads();
        // ---- load A chunk (128 x 32 fp32 -> bf16 hi/lo) ----
#pragma unroll
        for (int e = tid; e < 1024; e += 256) {
            int row = e >> 3, seg = (e & 7) << 2;
            float4 a = make_float4(0.f, 0.f, 0.f, 0.f);
            int gr = bm + row;
            if (gr < M) a = *reinterpret_cast<const float4*>(&A[(size_t)gr * K + kc + seg]);
            __nv_bfloat16 h0 = __float2bfloat16(a.x), h1 = __float2bfloat16(a.y);
            __nv_bfloat16 h2 = __float2bfloat16(a.z), h3 = __float2bfloat16(a.w);
            uint2 uh, ul;
            uh.x = ((uint32_t)*(uint16_t*)&h1 << 16) | *(uint16_t*)&h0;
            uh.y = ((uint32_t)*(uint16_t*)&h3 << 16) | *(uint16_t*)&h2;
            ul.x = pack_bf16x2(a.x - __bfloat162float(h0), a.y - __bfloat162float(h1));
            ul.y = pack_bf16x2(a.z - __bfloat162float(h2), a.w - __bfloat162float(h3));
            *reinterpret_cast<uint2*>(&sAh[row][seg]) = uh;
            *reinterpret_cast<uint2*>(&sAl[row][seg]) = ul;
        }
        // ---- load B chunk (128 x 32 bf16 hi/lo) ----
#pragma unroll
        for (int e = tid; e < 1024; e += 256) {
            int row = e >> 3, seg = (e & 7) << 2;
            size_t gi = (size_t)row * K + kc + seg;
            *reinterpret_cast<uint2*>(&sBh[row][seg]) = *reinterpret_cast<const uint2*>(&WhB[gi]);
            *reinterpret_cast<uint2*>(&sBl[row][seg]) = *reinterpret_cast<const uint2*>(&WlB[gi]);
        }
        __syncthreads();

#pragma unroll
        for (int ks = 0; ks < 2; ks++) {
            const int k0 = ks * 16;
            uint32_t ah[4][4], al[4][4], bh[4][2], bl[4][2];
#pragma unroll
            for (int mi = 0; mi < 4; mi++) {
                uint32_t adrh = (uint32_t)__cvta_generic_to_shared(&sAh[wm + mi * 16 + lrow][k0 + lcol]);
                uint32_t adrl = (uint32_t)__cvta_generic_to_shared(&sAl[wm + mi * 16 + lrow][k0 + lcol]);
                LDMX4(ah[mi][0], ah[mi][1], ah[mi][2], ah[mi][3], adrh);
                LDMX4(al[mi][0], al[mi][1], al[mi][2], al[mi][3], adrl);
            }
#pragma unroll
            for (int nj = 0; nj < 2; nj++) {
                uint32_t r0, r1, r2, r3;
                uint32_t adrh = (uint32_t)__cvta_generic_to_shared(&sBh[wn + nj * 16 + lrow][k0 + lcol]);
                LDMX4(r0, r1, r2, r3, adrh);
                bh[nj * 2 + 0][0] = r0; bh[nj * 2 + 0][1] = r2;
                bh[nj * 2 + 1][0] = r1; bh[nj * 2 + 1][1] = r3;
                uint32_t adrl = (uint32_t)__cvta_generic_to_shared(&sBl[wn + nj * 16 + lrow][k0 + lcol]);
                LDMX4(r0, r1, r2, r3, adrl);
                bl[nj * 2 + 0][0] = r0; bl[nj * 2 + 0][1] = r2;
                bl[nj * 2 + 1][0] = r1; bl[nj * 2 + 1][1] = r3;
            }
#pragma unroll
            for (int mi = 0; mi < 4; mi++)
#pragma unroll
                for (int nt = 0; nt < 4; nt++) {
                    MMA16816(acc[mi][nt], ah[mi], bh[nt]);
                    MMA16816(acc[mi][nt], al[mi], bh[nt]);
                    MMA16816(acc[mi][nt], ah[mi], bl[nt]);
                }
        }
    }

    // ---- epilogue ----
    const int trow = lane >> 2;
    const int tcol = (lane & 3) * 2;
#pragma unroll
    for (int mi = 0; mi < 4; mi++) {
        int r0 = bm + wm + mi * 16 + trow;
#pragma unroll
        for (int nt = 0; nt < 4; nt++) {
            int c0 = bn + wn + nt * 8 + tcol;
            if (r0 < M)
                *reinterpret_cast<float2*>(&C[(size_t)r0 * N + c0]) =
                    make_float2(acc[mi][nt][0], acc[mi][nt][1]);
            if (r0 + 8 < M)
                *reinterpret_cast<float2*>(&C[(size_t)(r0 + 8) * N + c0]) =
                    make_float2(acc[mi][nt][2], acc[mi][nt][3]);
        }
    }
}

// ---------------- 4) per-group prefix scan + bias + relu ----------------------
// grid (NGROUP, D/128), 128 threads; out[j] = relu(dis_j * prefix + b)
__global__ __launch_bounds__(128) void scan_relu(const float* __restrict__ H,
                                                 const float* __restrict__ bias,
                                                 float* __restrict__ out, int D) {
    __shared__ int   s_mem[MAXG];
    __shared__ float s_dis[MAXG];
    const int g = blockIdx.x;
    const int c = g_cnt[g];
    for (int m = threadIdx.x; m < c; m += 128) {
        int i = g_members[g * MAXG + m];
        s_mem[m] = i;
        s_dis[m] = g_dis[i];
    }
    __syncthreads();
    const int f = blockIdx.y * 128 + threadIdx.x;
    float acc = 0.0f;
    const float bf = bias[f];
    for (int m = 0; m < c; m++) {
        int   i = s_mem[m];
        float d = s_dis[m];
        acc = fmaf(d, H[(size_t)i * D + f], acc);
        out[(size_t)i * D + f] = fmaxf(fmaf(d, acc, bf), 0.0f);
    }
}

// ---------------- 5) LayerNorm over last dim (128) ----------------------------
__global__ __launch_bounds__(256) void layernorm128(const float* __restrict__ h,
                                                    const float* __restrict__ gamma,
                                                    const float* __restrict__ beta,
                                                    float* __restrict__ out, int n) {
    int row = blockIdx.x * (blockDim.x >> 5) + (threadIdx.x >> 5);
    if (row >= n) return;
    int lane = threadIdx.x & 31;
    float4 v = reinterpret_cast<const float4*>(h + (size_t)row * 128)[lane];
    float s = v.x + v.y + v.z + v.w;
#pragma unroll
    for (int o = 16; o; o >>= 1) s += __shfl_xor_sync(0xffffffffu, s, o);
    float mu = s * (1.0f / 128.0f);
    float dx = v.x - mu, dy = v.y - mu, dz = v.z - mu, dw = v.w - mu;
    float q = dx * dx + dy * dy + dz * dz + dw * dw;
#pragma unroll
    for (int o = 16; o; o >>= 1) q += __shfl_xor_sync(0xffffffffu, q, o);
    float inv = rsqrtf(q * (1.0f / 128.0f) + 1e-5f);
    float4 ga = reinterpret_cast<const float4*>(gamma)[lane];
    float4 be = reinterpret_cast<const float4*>(beta)[lane];
    float4 o4;
    o4.x = fmaf(dx * inv, ga.x, be.x);
    o4.y = fmaf(dy * inv, ga.y, be.y);
    o4.z = fmaf(dz * inv, ga.z, be.z);
    o4.w = fmaf(dw * inv, ga.w, be.w);
    reinterpret_cast<float4*>(out + (size_t)row * 128)[lane] = o4;
}

// ---------------- launch ------------------------------------------------------
extern "C" void kernel_launch(void* const* d_in, const int* in_sizes, int n_in,
                              void* d_out, int out_size) {
    const float* x     = (const float*)d_in[0];
    const void*  idx   = d_in[1];
    const float* W1    = (const float*)d_in[2];
    const float* b1    = (const float*)d_in[3];
    const float* W2    = (const float*)d_in[4];
    const float* b2    = (const float*)d_in[5];
    const float* W3    = (const float*)d_in[6];
    const float* b3    = (const float*)d_in[7];
    const float* gamma = (const float*)d_in[8];
    const float* beta  = (const float*)d_in[9];
    float* out = (float*)d_out;

    float *bufA = nullptr, *bufB = nullptr;
    __nv_bfloat16 *w1h, *w1l, *w2h, *w2l, *w3h, *w3l;
    cudaGetSymbolAddress((void**)&bufA, g_bufA);
    cudaGetSymbolAddress((void**)&bufB, g_bufB);
    cudaGetSymbolAddress((void**)&w1h, g_w1h);
    cudaGetSymbolAddress((void**)&w1l, g_w1l);
    cudaGetSymbolAddress((void**)&w2h, g_w2h);
    cudaGetSymbolAddress((void**)&w2l, g_w2l);
    cudaGetSymbolAddress((void**)&w3h, g_w3h);
    cudaGetSymbolAddress((void**)&w3l, g_w3l);

    const int n = NNODES;
    const int mtiles = (n + 127) / 128;  // 157

    detect_dtype<<<1, 256>>>((const int*)idx, n);
    build_groups<<<NGROUP, 256>>>(idx, n);
    prep_w<<<(128 * 256 + 255) / 256, 256>>>(W1, w1h, w1l, 128, 256);
    prep_w<<<(256 * 256 + 255) / 256, 256>>>(W2, w2h, w2l, 256, 256);
    prep_w<<<(256 * 128 + 255) / 256, 256>>>(W3, w3h, w3l, 256, 128);

    // layer 1: x[20000,128] @ W1 -> bufA[20000,256]
    gemm_mma<<<dim3(mtiles, 2), 256>>>(x, w1h, w1l, bufA, n, 128, 256);
    scan_relu<<<dim3(NGROUP, 2), 128>>>(bufA, b1, bufB, 256);
    // layer 2: [20000,256] @ W2 -> bufA
    gemm_mma<<<dim3(mtiles, 2), 256>>>(bufB, w2h, w2l, bufA, n, 256, 256);
    scan_relu<<<dim3(NGROUP, 2), 128>>>(bufA, b2, bufB, 256);
    // layer 3: [20000,256] @ W3 -> bufA (N=128)
    gemm_mma<<<dim3(mtiles, 1), 256>>>(bufB, w3h, w3l, bufA, n, 256, 128);
    scan_relu<<<dim3(NGROUP, 1), 128>>>(bufA, b3, bufB, 128);

    layernorm128<<<(n + 7) / 8, 256>>>(bufB, gamma, beta, out, n);
}